// round 7
// baseline (speedup 1.0000x reference)
#include <cuda_runtime.h>
#include <math.h>
#include <stdint.h>

#define NACC_MAX 200000
#define NMER_MAX 100000
#define E_MAX    500000

// ---------------- scratch (device globals; no allocations allowed) -------------
__device__ float g_xa[(size_t)NACC_MAX * 128];
__device__ float g_xm[(size_t)NMER_MAX * 128];
__device__ float g_ya[(size_t)NACC_MAX * 128];
__device__ float g_ym[(size_t)NMER_MAX * 128];
__device__ float g_agg[(size_t)NACC_MAX * 128];   // rev -> acc
__device__ float g_agg2[(size_t)NACC_MAX * 128];  // transfer -> acc
__device__ float g_aggm[(size_t)NMER_MAX * 128];  // pays -> mer
__device__ int   g_rowptr[3][NACC_MAX + 1];
__device__ int   g_csr[3][E_MAX];
__device__ int   g_deg[NACC_MAX];
__device__ int   g_cur[NACC_MAX];
__device__ int   g_bsum[1024];
// stats: [accP0 sum|sqs][accP1 sum|sqs][merP0 sum|sqs][merP1 sum|sqs], 256 floats each
__device__ float g_stat[8 * 128];

// ---------------- bf16x3 emulation helpers ---------------------------------------
__device__ __forceinline__ void split2(float2 v, uint32_t& h, uint32_t& l) {
    uint32_t u0 = __float_as_uint(v.x), u1 = __float_as_uint(v.y);
    h = __byte_perm(u0, u1, 0x7632);
    float r0 = v.x - __uint_as_float(u0 & 0xFFFF0000u);
    float r1 = v.y - __uint_as_float(u1 & 0xFFFF0000u);
    asm("cvt.rn.bf16x2.f32 %0, %1, %2;" : "=r"(l) : "f"(r1), "f"(r0));
}

__device__ __forceinline__ void mma_bf16(float* d, const uint32_t* a,
                                         uint32_t b0, uint32_t b1) {
    asm volatile(
        "mma.sync.aligned.m16n8k16.row.col.f32.bf16.bf16.f32 "
        "{%0,%1,%2,%3}, {%4,%5,%6,%7}, {%8,%9}, {%0,%1,%2,%3};"
        : "+f"(d[0]), "+f"(d[1]), "+f"(d[2]), "+f"(d[3])
        : "r"(a[0]), "r"(a[1]), "r"(a[2]), "r"(a[3]), "r"(b0), "r"(b1));
}

__device__ __forceinline__ uint32_t saddr(const void* p) {
    uint32_t a;
    asm("{ .reg .u64 t; cvta.to.shared.u64 t, %1; cvt.u32.u64 %0, t; }"
        : "=r"(a) : "l"(p));
    return a;
}

__device__ __forceinline__ void cp16(uint32_t dst, const void* src, bool pred) {
    asm volatile("cp.async.cg.shared.global [%0], [%1], 16, %2;"
                 :: "r"(dst), "l"(src), "r"(pred ? 16 : 0) : "memory");
}
__device__ __forceinline__ void cp_commit() {
    asm volatile("cp.async.commit_group;" ::: "memory");
}

// ---------------- CSR build ------------------------------------------------------
__global__ void hist_kernel(const int* __restrict__ ei, int E, int* __restrict__ deg) {
    int e = blockIdx.x * blockDim.x + threadIdx.x;
    if (e >= E) return;
    atomicAdd(&deg[ei[E + e]], 1);
}

__global__ void scan1(const int* __restrict__ deg, int n,
                      int* __restrict__ rowptr, int* __restrict__ bsum) {
    __shared__ int s[1024];
    int i = blockIdx.x * 1024 + threadIdx.x;
    int v = (i < n) ? deg[i] : 0;
    s[threadIdx.x] = v;
    __syncthreads();
    for (int off = 1; off < 1024; off <<= 1) {
        int t = (threadIdx.x >= off) ? s[threadIdx.x - off] : 0;
        __syncthreads();
        s[threadIdx.x] += t;
        __syncthreads();
    }
    if (i < n) rowptr[i + 1] = s[threadIdx.x];
    if (threadIdx.x == 1023) bsum[blockIdx.x] = s[1023];
}

__global__ void scan2(int* __restrict__ bsum, int nb) {
    __shared__ int s[1024];
    int v = (threadIdx.x < nb) ? bsum[threadIdx.x] : 0;
    s[threadIdx.x] = v;
    __syncthreads();
    for (int off = 1; off < 1024; off <<= 1) {
        int t = (threadIdx.x >= off) ? s[threadIdx.x - off] : 0;
        __syncthreads();
        s[threadIdx.x] += t;
        __syncthreads();
    }
    if (threadIdx.x < nb) bsum[threadIdx.x] = s[threadIdx.x] - v;  // exclusive
}

__global__ void scan3(int n, int* __restrict__ rowptr, const int* __restrict__ bsum) {
    int i = blockIdx.x * blockDim.x + threadIdx.x;
    if (i < n) rowptr[i + 1] += bsum[i >> 10];
    if (i == 0) rowptr[0] = 0;
}

__global__ void scatter_kernel(const int* __restrict__ ei, int E,
                               int* __restrict__ cur, int* __restrict__ csr) {
    int e = blockIdx.x * blockDim.x + threadIdx.x;
    if (e >= E) return;
    int src = ei[e], dst = ei[E + e];
    int pos = atomicAdd(&cur[dst], 1);
    csr[pos] = src;
}

// ---------------- fused mean aggregation with on-the-fly BN+ReLU ----------------
struct SegParams {
    int n;
    const int* rp; const int* cs;
    const float* src; float* out;
    const float* sum; const float* sqs;   // nullptr -> identity (no BN)
    const float* g; const float* b;
    float invn; int relu;
};

__global__ __launch_bounds__(256)
void agg_all(SegParams s0, SegParams s1, SegParams s2)
{
    int w = (blockIdx.x * blockDim.x + threadIdx.x) >> 5;
    int lane = threadIdx.x & 31;
    const SegParams* S; int d;
    if (w < s0.n)                { S = &s0; d = w; }
    else if (w < s0.n + s1.n)    { S = &s1; d = w - s0.n; }
    else if (w < s0.n + s1.n + s2.n) { S = &s2; d = w - s0.n - s1.n; }
    else return;

    // per-lane BN scale/shift for the 4 feature dims this lane owns
    float4 sc = make_float4(1.f, 1.f, 1.f, 1.f);
    float4 sh = make_float4(0.f, 0.f, 0.f, 0.f);
    if (S->sum) {
        float4 sm4 = __ldg(reinterpret_cast<const float4*>(S->sum) + lane);
        float4 sq4 = __ldg(reinterpret_cast<const float4*>(S->sqs) + lane);
        float4 g4  = __ldg(reinterpret_cast<const float4*>(S->g) + lane);
        float4 b4  = __ldg(reinterpret_cast<const float4*>(S->b) + lane);
        float invn = S->invn;
#pragma unroll
        for (int c = 0; c < 4; c++) {
            float mu = (&sm4.x)[c] * invn;
            float var = (&sq4.x)[c] * invn - mu * mu;
            float iv = rsqrtf(var + 1e-5f);
            float s = (&g4.x)[c] * iv;
            (&sc.x)[c] = s;
            (&sh.x)[c] = (&b4.x)[c] - mu * s;
        }
    }
    int relu = S->relu;

    int s = __ldg(&S->rp[d]), e = __ldg(&S->rp[d + 1]);
    const float* src = S->src;
    const int* cs = S->cs;
    float4 acc = make_float4(0.f, 0.f, 0.f, 0.f);
    for (int i = s; i < e; i++) {
        int s0i = __ldg(&cs[i]);
        float4 v = __ldg(reinterpret_cast<const float4*>(src + (size_t)s0i * 128) + lane);
        v.x = v.x * sc.x + sh.x; v.y = v.y * sc.y + sh.y;
        v.z = v.z * sc.z + sh.z; v.w = v.w * sc.w + sh.w;
        if (relu) {
            v.x = fmaxf(v.x, 0.f); v.y = fmaxf(v.y, 0.f);
            v.z = fmaxf(v.z, 0.f); v.w = fmaxf(v.w, 0.f);
        }
        acc.x += v.x; acc.y += v.y; acc.z += v.z; acc.w += v.w;
    }
    float inv = 1.f / fmaxf((float)(e - s), 1.f);
    acc.x *= inv; acc.y *= inv; acc.z *= inv; acc.w *= inv;
    *(reinterpret_cast<float4*>(S->out + (size_t)d * 128) + lane) = acc;
}

// ---------------- bf16x3 pipelined GEMM with fused BN-on-xdst --------------------
// D[128, DO] per CTA = A[128, K] @ B[DO, K]^T
// MODE 0: A = A1[n,K] raw (input projection), epilogue = +bias.
// MODE 1: K=256, A = [mean_agg | bn_relu(ydst)]; BN (psum..) applied on the fly to
//         k>=128 columns. Epilogue = +bias, row L2-norm, optional += (HeteroConv).
// STATS : fused BatchNorm column sum/sumsq of the final output values.
// 256 threads = 8 warps, 2(m) x 4(n); warp tile 64m x (DO/4)n; BK=16; 3-stage
// cp.async pipeline, one __syncthreads per tile; 2 CTAs/SM.
template<int DO, int MODE, bool ACCUM, bool STATS>
__global__ __launch_bounds__(256, 2)
void mma_gemm(int n, int K,
              const float* __restrict__ A1, const float* __restrict__ A2,
              const float* __restrict__ B1, const float* __restrict__ B2,
              const float* __restrict__ bias, float* __restrict__ C,
              float* __restrict__ gsum, float* __restrict__ gsqs,
              const float* __restrict__ psum, const float* __restrict__ psqs,
              const float* __restrict__ pg, const float* __restrict__ pb,
              float pinvn, int prelu)
{
    constexpr int NJ = DO / 32;
    extern __shared__ float smf[];
    float (*As)[128][20] = reinterpret_cast<float(*)[128][20]>(smf);
    float (*Bs)[128][20] = reinterpret_cast<float(*)[128][20]>(smf + 3 * 128 * 20);
    float* sBias = smf + 6 * 128 * 20;
    float* sSc   = sBias + 128;
    float* sSh   = sSc + 128;
    float* ssRow = sSh + 128;
    float* sCS   = ssRow + 128;
    float* sCQ   = sCS + 128;

    int tid = threadIdx.x, lane = tid & 31, warp = tid >> 5;
    int g = lane >> 2, t = lane & 3;
    int wm = warp & 1, wn = warp >> 1;
    int row0 = blockIdx.x * 128;

    if (tid < DO) {
        sBias[tid] = bias[tid];
        if (STATS) { sCS[tid] = 0.f; sCQ[tid] = 0.f; }
    }
    if (tid < 128) {
        ssRow[tid] = 0.f;
        if (MODE == 1) {
            float sc = 1.f, sh = 0.f;
            if (psum) {
                float mu = psum[tid] * pinvn;
                float var = psqs[tid] * pinvn - mu * mu;
                float iv = rsqrtf(var + 1e-5f);
                sc = pg[tid] * iv;
                sh = pb[tid] - mu * sc;
            }
            sSc[tid] = sc; sSh[tid] = sh;
        }
    }

    float acc[4][NJ][4];
#pragma unroll
    for (int i = 0; i < 4; i++)
#pragma unroll
        for (int j = 0; j < NJ; j++)
#pragma unroll
            for (int c = 0; c < 4; c++) acc[i][j][c] = 0.f;

    const int T = K >> 4;

    auto load_tile = [&](int kt, int buf) {
#pragma unroll
        for (int h = 0; h < 2; h++) {
            int idx = tid + h * 256;
            int m = idx >> 2, q = idx & 3;
            int k = kt * 16 + q * 4;
            int r = row0 + m;
            bool p = (r < n);
            int rc = p ? r : 0;
            const float* src;
            if (MODE == 0) src = A1 + (size_t)rc * K + k;
            else src = (k < 128) ? A1 + (size_t)rc * 128 + k
                                 : A2 + (size_t)rc * 128 + (k - 128);
            cp16(saddr(&As[buf][m][q * 4]), src, p);
        }
        // B tile: DO*4 float4 loads; loop twice with guard (fixes R6 bug where
        // only 256 of 512 loads happened for DO=128)
#pragma unroll
        for (int h = 0; h < 2; h++) {
            int idx = tid + h * 256;
            if (idx < DO * 4) {
                int j = idx >> 2, q = idx & 3, k = kt * 16 + q * 4;
                const float* src;
                if (MODE == 1) src = (k < 128) ? B1 + (size_t)j * 128 + k
                                               : B2 + (size_t)j * 128 + (k - 128);
                else src = B1 + (size_t)j * K + k;
                cp16(saddr(&Bs[buf][j][q * 4]), src, true);
            }
        }
    };

    auto compute = [&](int kt, int buf) {
        bool tr = (MODE == 1) && (kt >= 8);
        float2 sca, scb, sha, shb;
        if (tr) {
            int kb = (kt - 8) * 16;
            sca = *reinterpret_cast<const float2*>(&sSc[kb + 2 * t]);
            scb = *reinterpret_cast<const float2*>(&sSc[kb + 2 * t + 8]);
            sha = *reinterpret_cast<const float2*>(&sSh[kb + 2 * t]);
            shb = *reinterpret_cast<const float2*>(&sSh[kb + 2 * t + 8]);
        }
        // B fragments held across i-loop
        uint32_t bh[NJ][2], bl[NJ][2];
#pragma unroll
        for (int j = 0; j < NJ; j++) {
            int nb = wn * (NJ * 8) + j * 8 + g;
            float2 w0 = *reinterpret_cast<const float2*>(&Bs[buf][nb][2 * t]);
            float2 w1 = *reinterpret_cast<const float2*>(&Bs[buf][nb][2 * t + 8]);
            split2(w0, bh[j][0], bl[j][0]);
            split2(w1, bh[j][1], bl[j][1]);
        }
#pragma unroll
        for (int i = 0; i < 4; i++) {
            int rb = wm * 64 + i * 16;
            float2 v0 = *reinterpret_cast<const float2*>(&As[buf][rb + g][2 * t]);
            float2 v1 = *reinterpret_cast<const float2*>(&As[buf][rb + g + 8][2 * t]);
            float2 v2 = *reinterpret_cast<const float2*>(&As[buf][rb + g][2 * t + 8]);
            float2 v3 = *reinterpret_cast<const float2*>(&As[buf][rb + g + 8][2 * t + 8]);
            if (tr) {
                v0.x = v0.x * sca.x + sha.x; v0.y = v0.y * sca.y + sha.y;
                v1.x = v1.x * sca.x + sha.x; v1.y = v1.y * sca.y + sha.y;
                v2.x = v2.x * scb.x + shb.x; v2.y = v2.y * scb.y + shb.y;
                v3.x = v3.x * scb.x + shb.x; v3.y = v3.y * scb.y + shb.y;
                if (prelu) {
                    v0.x = fmaxf(v0.x, 0.f); v0.y = fmaxf(v0.y, 0.f);
                    v1.x = fmaxf(v1.x, 0.f); v1.y = fmaxf(v1.y, 0.f);
                    v2.x = fmaxf(v2.x, 0.f); v2.y = fmaxf(v2.y, 0.f);
                    v3.x = fmaxf(v3.x, 0.f); v3.y = fmaxf(v3.y, 0.f);
                }
            }
            uint32_t ah[4], al[4];
            split2(v0, ah[0], al[0]);
            split2(v1, ah[1], al[1]);
            split2(v2, ah[2], al[2]);
            split2(v3, ah[3], al[3]);
#pragma unroll
            for (int j = 0; j < NJ; j++) {
                mma_bf16(acc[i][j], ah, bh[j][0], bh[j][1]);
                mma_bf16(acc[i][j], ah, bl[j][0], bl[j][1]);
                mma_bf16(acc[i][j], al, bh[j][0], bh[j][1]);
            }
        }
    };

    // 3-stage pipeline, one syncthreads per tile
    load_tile(0, 0); cp_commit();
    if (T > 1) { load_tile(1, 1); cp_commit(); }
    for (int kt = 0; kt < T; kt++) {
        if (kt + 1 < T) asm volatile("cp.async.wait_group 1;" ::: "memory");
        else            asm volatile("cp.async.wait_group 0;" ::: "memory");
        __syncthreads();
        if (kt + 2 < T) { load_tile(kt + 2, (kt + 2) % 3); cp_commit(); }
        compute(kt, kt % 3);
    }

    // ---- epilogue: bias, row L2-norm, accumulate, fused BN stats ----
#pragma unroll
    for (int i = 0; i < 4; i++) {
        float ss0 = 0.f, ss1 = 0.f;
#pragma unroll
        for (int j = 0; j < NJ; j++) {
            int cb = wn * (NJ * 8) + j * 8 + t * 2;
            float b0 = sBias[cb], b1 = sBias[cb + 1];
            acc[i][j][0] += b0; acc[i][j][1] += b1;
            acc[i][j][2] += b0; acc[i][j][3] += b1;
            if (MODE == 1) {
                ss0 += acc[i][j][0] * acc[i][j][0] + acc[i][j][1] * acc[i][j][1];
                ss1 += acc[i][j][2] * acc[i][j][2] + acc[i][j][3] * acc[i][j][3];
            }
        }
        if (MODE == 1) {
            ss0 += __shfl_xor_sync(0xffffffffu, ss0, 1);
            ss0 += __shfl_xor_sync(0xffffffffu, ss0, 2);
            ss1 += __shfl_xor_sync(0xffffffffu, ss1, 1);
            ss1 += __shfl_xor_sync(0xffffffffu, ss1, 2);
            if (t == 0) {
                atomicAdd(&ssRow[wm * 64 + i * 16 + g], ss0);
                atomicAdd(&ssRow[wm * 64 + i * 16 + g + 8], ss1);
            }
        }
    }
    __syncthreads();

    float cs[NJ][2], cq[NJ][2];
    if (STATS) {
#pragma unroll
        for (int j = 0; j < NJ; j++) { cs[j][0] = cs[j][1] = cq[j][0] = cq[j][1] = 0.f; }
    }

#pragma unroll
    for (int i = 0; i < 4; i++) {
        int rl = wm * 64 + i * 16 + g;
        float s0 = 1.f, s1 = 1.f;
        if (MODE == 1) {
            s0 = 1.f / fmaxf(sqrtf(ssRow[rl]), 1e-12f);
            s1 = 1.f / fmaxf(sqrtf(ssRow[rl + 8]), 1e-12f);
        }
        int r0 = row0 + rl, r1 = r0 + 8;
#pragma unroll
        for (int j = 0; j < NJ; j++) {
            int cb = wn * (NJ * 8) + j * 8 + t * 2;
            if (r0 < n) {
                float2* p = reinterpret_cast<float2*>(C + (size_t)r0 * DO + cb);
                float2 v = make_float2(acc[i][j][0] * s0, acc[i][j][1] * s0);
                if (ACCUM) { float2 o = *p; v.x += o.x; v.y += o.y; }
                *p = v;
                if (STATS) {
                    cs[j][0] += v.x; cs[j][1] += v.y;
                    cq[j][0] += v.x * v.x; cq[j][1] += v.y * v.y;
                }
            }
            if (r1 < n) {
                float2* p = reinterpret_cast<float2*>(C + (size_t)r1 * DO + cb);
                float2 v = make_float2(acc[i][j][2] * s1, acc[i][j][3] * s1);
                if (ACCUM) { float2 o = *p; v.x += o.x; v.y += o.y; }
                *p = v;
                if (STATS) {
                    cs[j][0] += v.x; cs[j][1] += v.y;
                    cq[j][0] += v.x * v.x; cq[j][1] += v.y * v.y;
                }
            }
        }
    }

    if (STATS) {
#pragma unroll
        for (int j = 0; j < NJ; j++)
#pragma unroll
            for (int c = 0; c < 2; c++) {
                float s = cs[j][c], q = cq[j][c];
                s += __shfl_xor_sync(0xffffffffu, s, 4);
                s += __shfl_xor_sync(0xffffffffu, s, 8);
                s += __shfl_xor_sync(0xffffffffu, s, 16);
                q += __shfl_xor_sync(0xffffffffu, q, 4);
                q += __shfl_xor_sync(0xffffffffu, q, 8);
                q += __shfl_xor_sync(0xffffffffu, q, 16);
                if (g == 0) {
                    int cb = wn * (NJ * 8) + j * 8 + t * 2 + c;
                    atomicAdd(&sCS[cb], s);
                    atomicAdd(&sCQ[cb], q);
                }
            }
        __syncthreads();
        if (tid < DO) {
            atomicAdd(&gsum[tid], sCS[tid]);
            atomicAdd(&gsqs[tid], sCQ[tid]);
        }
    }
}

// ---------------- classifier with fused final BN (no relu): --------------------
// logits = relu(bn(y) @ W1^T + b1) @ W2^T + b2
__global__ __launch_bounds__(256)
void classifier_kernel(const float* __restrict__ X, int n,
                       const float* __restrict__ W1, const float* __restrict__ b1,
                       const float* __restrict__ W2, const float* __restrict__ b2,
                       float* __restrict__ out,
                       const float* __restrict__ psum, const float* __restrict__ psqs,
                       const float* __restrict__ pg, const float* __restrict__ pb,
                       float pinvn)
{
    __shared__ float sW1[64 * 65];
    __shared__ float sW2[64];
    __shared__ float sb1[64];
    __shared__ float ssc[64], ssh[64];
    int tid = threadIdx.x;
    for (int i = tid; i < 64 * 64; i += 256) {
        int j = i >> 6, k = i & 63;
        sW1[j * 65 + k] = W1[i];
    }
    if (tid < 64) {
        sW2[tid] = W2[tid]; sb1[tid] = b1[tid];
        float mu = psum[tid] * pinvn;
        float var = psqs[tid] * pinvn - mu * mu;
        float iv = rsqrtf(var + 1e-5f);
        float sc = pg[tid] * iv;
        ssc[tid] = sc;
        ssh[tid] = pb[tid] - mu * sc;
    }
    __syncthreads();

    int lane = tid & 31;
    int row = blockIdx.x * 8 + (tid >> 5);
    if (row >= n) return;
    float x0 = X[(size_t)row * 64 + lane] * ssc[lane] + ssh[lane];
    float x1 = X[(size_t)row * 64 + 32 + lane] * ssc[lane + 32] + ssh[lane + 32];
    float h0 = sb1[lane], h1 = sb1[lane + 32];
#pragma unroll
    for (int k = 0; k < 32; k++) {
        float xk = __shfl_sync(0xffffffffu, x0, k);
        h0 += xk * sW1[lane * 65 + k];
        h1 += xk * sW1[(lane + 32) * 65 + k];
    }
#pragma unroll
    for (int k = 0; k < 32; k++) {
        float xk = __shfl_sync(0xffffffffu, x1, k);
        h0 += xk * sW1[lane * 65 + 32 + k];
        h1 += xk * sW1[(lane + 32) * 65 + 32 + k];
    }
    h0 = fmaxf(h0, 0.f); h1 = fmaxf(h1, 0.f);
    float p = h0 * sW2[lane] + h1 * sW2[lane + 32];
#pragma unroll
    for (int off = 16; off; off >>= 1)
        p += __shfl_xor_sync(0xffffffffu, p, off);
    if (lane == 0) out[row] = p + b2[0];
}

// ---------------- host-side CSR build --------------------------------------------
static void build_csr(const int* ei, int E, int ndst,
                      int* rowptr, int* csr, int* deg, int* cur, int* bsum)
{
    cudaMemsetAsync(deg, 0, (size_t)ndst * sizeof(int), 0);
    hist_kernel<<<(E + 255) / 256, 256>>>(ei, E, deg);
    int nb = (ndst + 1023) / 1024;
    scan1<<<nb, 1024>>>(deg, ndst, rowptr, bsum);
    scan2<<<1, 1024>>>(bsum, nb);
    scan3<<<(ndst + 255) / 256, 256>>>(ndst, rowptr, bsum);
    cudaMemcpyAsync(cur, rowptr, (size_t)ndst * sizeof(int),
                    cudaMemcpyDeviceToDevice, 0);
    scatter_kernel<<<(E + 255) / 256, 256>>>(ei, E, cur, csr);
}

#define SMEM_GEMM (16128 * 4)

// ---------------- kernel_launch -------------------------------------------------
extern "C" void kernel_launch(void* const* d_in, const int* in_sizes, int n_in,
                              void* d_out, int out_size)
{
    const float* x_acc      = (const float*)d_in[0];
    const float* x_mer      = (const float*)d_in[1];
    const int*   ei_pays    = (const int*)d_in[2];
    const int*   ei_rev     = (const int*)d_in[3];
    const int*   ei_tr      = (const int*)d_in[4];
    const float* projW_acc  = (const float*)d_in[5];
    const float* projb_acc  = (const float*)d_in[6];
    const float* projW_mer  = (const float*)d_in[7];
    const float* projb_mer  = (const float*)d_in[8];
    const float* Wl[3] = {(const float*)d_in[9],  (const float*)d_in[12], (const float*)d_in[15]};
    const float* bl[3] = {(const float*)d_in[10], (const float*)d_in[13], (const float*)d_in[16]};
    const float* Wr[3] = {(const float*)d_in[11], (const float*)d_in[14], (const float*)d_in[17]};
    const float* bng[3] = {(const float*)d_in[18], (const float*)d_in[20], (const float*)d_in[22]};
    const float* bnb[3] = {(const float*)d_in[19], (const float*)d_in[21], (const float*)d_in[23]};
    const float* clfW1 = (const float*)d_in[24];
    const float* clfb1 = (const float*)d_in[25];
    const float* clfW2 = (const float*)d_in[26];
    const float* clfb2 = (const float*)d_in[27];
    float* out = (float*)d_out;

    int nacc = in_sizes[0] / 64;
    int nmer = in_sizes[1] / 32;
    int E    = in_sizes[2] / 2;
    float invA = 1.f / (float)nacc, invM = 1.f / (float)nmer;

    float *xa, *xm, *ya, *ym, *agg, *agg2, *aggm, *stat;
    int *rowptr, *csr, *deg, *cur, *bsum;
    cudaGetSymbolAddress((void**)&xa,     g_xa);
    cudaGetSymbolAddress((void**)&xm,     g_xm);
    cudaGetSymbolAddress((void**)&ya,     g_ya);
    cudaGetSymbolAddress((void**)&ym,     g_ym);
    cudaGetSymbolAddress((void**)&agg,    g_agg);
    cudaGetSymbolAddress((void**)&agg2,   g_agg2);
    cudaGetSymbolAddress((void**)&aggm,   g_aggm);
    cudaGetSymbolAddress((void**)&stat,   g_stat);
    cudaGetSymbolAddress((void**)&rowptr, g_rowptr);
    cudaGetSymbolAddress((void**)&csr,    g_csr);
    cudaGetSymbolAddress((void**)&deg,    g_deg);
    cudaGetSymbolAddress((void**)&cur,    g_cur);
    cudaGetSymbolAddress((void**)&bsum,   g_bsum);

    int* rp[3]  = {rowptr, rowptr + (NACC_MAX + 1), rowptr + 2 * (NACC_MAX + 1)};
    int* cs3[3] = {csr, csr + E_MAX, csr + 2 * E_MAX};
    float* stA[2] = {stat, stat + 256};          // [sum|sqs] per parity
    float* stM[2] = {stat + 512, stat + 768};

    // opt-in dynamic smem for all GEMM instantiations
    cudaFuncSetAttribute(mma_gemm<128, 0, false, false>, cudaFuncAttributeMaxDynamicSharedMemorySize, SMEM_GEMM);
    cudaFuncSetAttribute(mma_gemm<128, 1, false, true >, cudaFuncAttributeMaxDynamicSharedMemorySize, SMEM_GEMM);
    cudaFuncSetAttribute(mma_gemm<128, 1, false, false>, cudaFuncAttributeMaxDynamicSharedMemorySize, SMEM_GEMM);
    cudaFuncSetAttribute(mma_gemm<128, 1, true,  true >, cudaFuncAttributeMaxDynamicSharedMemorySize, SMEM_GEMM);
    cudaFuncSetAttribute(mma_gemm<64,  1, false, false>, cudaFuncAttributeMaxDynamicSharedMemorySize, SMEM_GEMM);
    cudaFuncSetAttribute(mma_gemm<64,  1, true,  true >, cudaFuncAttributeMaxDynamicSharedMemorySize, SMEM_GEMM);

    // --- CSR builds (one per edge type, reused across layers) ---
    build_csr(ei_pays, E, nmer, rp[0], cs3[0], deg, cur, bsum);
    build_csr(ei_rev,  E, nacc, rp[1], cs3[1], deg, cur, bsum);
    build_csr(ei_tr,   E, nacc, rp[2], cs3[2], deg, cur, bsum);

    int agrid = (nacc + 127) / 128;
    int mgrid = (nmer + 127) / 128;

    // --- input projections (raw linear, no BN) ---
    mma_gemm<128, 0, false, false><<<agrid, 256, SMEM_GEMM>>>(nacc, 64, x_acc, nullptr,
        projW_acc, nullptr, projb_acc, xa, nullptr, nullptr,
        nullptr, nullptr, nullptr, nullptr, 0.f, 0);
    mma_gemm<128, 0, false, false><<<mgrid, 256, SMEM_GEMM>>>(nmer, 32, x_mer, nullptr,
        projW_mer, nullptr, projb_mer, xm, nullptr, nullptr,
        nullptr, nullptr, nullptr, nullptr, 0.f, 0);

    // ping-pong feature buffers (pre-BN), stats carried separately
    float* accSrc[3] = {xa, ya, xa};
    float* accDst[3] = {ya, xa, ya};
    float* merSrc[3] = {xm, ym, xm};
    float* merDst[3] = {ym, xm, nullptr};

    int douts[3] = {128, 128, 64};
    for (int L = 0; L < 3; L++) {
        int DO = douts[L];
        int pL = L & 1;
        // previous-layer stats (nullptr at L=0 -> identity, no relu)
        const float* pAs = (L > 0) ? stA[(L - 1) & 1] : nullptr;
        const float* pAq = pAs ? pAs + 128 : nullptr;
        const float* pMs = (L > 0) ? stM[(L - 1) & 1] : nullptr;
        const float* pMq = pMs ? pMs + 128 : nullptr;
        const float* gA = (L > 0) ? bng[L - 1] + 0 : nullptr;       // acc gamma
        const float* bA = (L > 0) ? bnb[L - 1] + 0 : nullptr;
        const float* gM = (L > 0) ? bng[L - 1] + 128 : nullptr;     // mer gamma
        const float* bM = (L > 0) ? bnb[L - 1] + 128 : nullptr;
        int relu = (L > 0) ? 1 : 0;
        int n0 = (L < 2) ? nmer : 0;   // pays dead at L==2

        // --- all aggregations for this layer in one launch (BN+ReLU on the fly) ---
        SegParams s0 = {n0,   rp[0], cs3[0], accSrc[L], aggm, pAs, pAq, gA, bA, invA, relu};
        SegParams s1 = {nacc, rp[1], cs3[1], merSrc[L], agg,  pMs, pMq, gM, bM, invM, relu};
        SegParams s2 = {nacc, rp[2], cs3[2], accSrc[L], agg2, pAs, pAq, gA, bA, invA, relu};
        int twarp = n0 + nacc + nacc;
        agg_all<<<(twarp * 32 + 255) / 256, 256>>>(s0, s1, s2);

        // (a) pays: acc -> mer; emits merchant BN stats
        if (L < 2) {
            cudaMemsetAsync(stM[pL], 0, 256 * sizeof(float), 0);
            mma_gemm<128, 1, false, true><<<mgrid, 256, SMEM_GEMM>>>(nmer, 256, aggm,
                merSrc[L],
                Wl[L] + 0 * (size_t)DO * 128, Wr[L] + 0 * (size_t)DO * 128,
                bl[L] + 0 * DO, merDst[L], stM[pL], stM[pL] + 128,
                pMs, pMq, gM, bM, invM, relu);
        }

        // (b) rev: mer -> acc (no stats: not final value yet)
        if (DO == 128)
            mma_gemm<128, 1, false, false><<<agrid, 256, SMEM_GEMM>>>(nacc, 256, agg,
                accSrc[L],
                Wl[L] + 1 * (size_t)DO * 128, Wr[L] + 1 * (size_t)DO * 128,
                bl[L] + 1 * DO, accDst[L], nullptr, nullptr,
                pAs, pAq, gA, bA, invA, relu);
        else
            mma_gemm<64, 1, false, false><<<agrid, 256, SMEM_GEMM>>>(nacc, 256, agg,
                accSrc[L],
                Wl[L] + 1 * (size_t)DO * 128, Wr[L] + 1 * (size_t)DO * 128,
                bl[L] + 1 * DO, accDst[L], nullptr, nullptr,
                pAs, pAq, gA, bA, invA, relu);

        // (c) transfer: acc -> acc (HeteroConv +=); emits account BN stats
        cudaMemsetAsync(stA[pL], 0, 256 * sizeof(float), 0);
        if (DO == 128)
            mma_gemm<128, 1, true, true><<<agrid, 256, SMEM_GEMM>>>(nacc, 256, agg2,
                accSrc[L],
                Wl[L] + 2 * (size_t)DO * 128, Wr[L] + 2 * (size_t)DO * 128,
                bl[L] + 2 * DO, accDst[L], stA[pL], stA[pL] + 128,
                pAs, pAq, gA, bA, invA, relu);
        else
            mma_gemm<64, 1, true, true><<<agrid, 256, SMEM_GEMM>>>(nacc, 256, agg2,
                accSrc[L],
                Wl[L] + 2 * (size_t)DO * 128, Wr[L] + 2 * (size_t)DO * 128,
                bl[L] + 2 * DO, accDst[L], stA[pL], stA[pL] + 128,
                pAs, pAq, gA, bA, invA, relu);
    }

    // --- classifier head on accounts (fused final BN, no relu) ---
    classifier_kernel<<<(nacc + 7) / 8, 256>>>(ya, nacc, clfW1, clfb1, clfW2, clfb2, out,
                                               stA[0], stA[0] + 128,
                                               bng[2], bnb[2], invA);
}